// round 2
// baseline (speedup 1.0000x reference)
#include <cuda_runtime.h>
#include <cuda_bf16.h>
#include <cstdint>

// out[v, g, v2, d] = W[GE[v,g] % 3, d] + b[d],  shapes:
//   GE: [512, 4, 1] int32 (JAX x64 disabled -> "int64" is really int32),
//   W: [3, 64] f32, b: [64] f32
//   out: [512, 4, 512, 64] f32  (256 MB) — value constant along v2.
//
// One block per (v,g) pair. Each thread owns one float4 of the 64-float
// embedding vector, computes it once, and streams 32 coalesced STG.128s.

static constexpr int V = 512;
static constexpr int G = 4;
static constexpr int D = 64;
static constexpr int D4 = D / 4;          // 16 float4 per embedding row
static constexpr int THREADS = 256;

__global__ void __launch_bounds__(THREADS, 8)
gembed_bcast_kernel(const int* __restrict__ GE,
                    const float* __restrict__ W,
                    const float* __restrict__ b,
                    float4* __restrict__ out)
{
    const int pair = blockIdx.x;              // v*G + g, 0..2047
    const int t    = threadIdx.x;             // 0..255
    const int d4   = t & (D4 - 1);            // which float4 of the row

    // Gather the embedding value for this thread's float4 slot.
    const int idx = GE[pair] % 3;             // GE in [0,3)

    const float4 w  = reinterpret_cast<const float4*>(W + idx * D)[d4];
    const float4 bb = reinterpret_cast<const float4*>(b)[d4];
    float4 val;
    val.x = w.x + bb.x;
    val.y = w.y + bb.y;
    val.z = w.z + bb.z;
    val.w = w.w + bb.w;

    // Stream 512 copies of the 64-float row. Warp writes 512 contiguous bytes
    // per iteration (2 copy-rows x 16 float4); each thread does 32 stores.
    float4* base = out + (size_t)pair * (size_t)V * (size_t)D4;
    const int c0 = t >> 4;                    // starting copy row (0..15)

    #pragma unroll 8
    for (int c = c0; c < V; c += THREADS / D4) {
        base[c * D4 + d4] = val;
    }
}

extern "C" void kernel_launch(void* const* d_in, const int* in_sizes, int n_in,
                              void* d_out, int out_size)
{
    const int*   GE = (const int*)d_in[0];
    const float* W  = (const float*)d_in[1];
    const float* b  = (const float*)d_in[2];
    float4* out = (float4*)d_out;

    (void)in_sizes; (void)n_in; (void)out_size;

    gembed_bcast_kernel<<<V * G, THREADS>>>(GE, W, b, out);
}

// round 3
// speedup vs baseline: 1.0059x; 1.0059x over previous
#include <cuda_runtime.h>
#include <cuda_bf16.h>
#include <cstdint>

// out[v, g, v2, d] = W[GE[v,g] % 3, d] + b[d]
//   GE: [512, 4, 1] int32, W: [3, 64] f32, b: [64] f32
//   out: [512, 4, 512, 64] f32  (256 MB) — value constant along v2.
//
// One block per (v,g) pair. Each thread owns 8 floats (32 B) of the 64-float
// embedding row, computes once, and streams 16 copies via 256-bit
// st.global.v8.b32 (sm_100+) — halves L1tex wavefronts vs STG.128.

static constexpr int V = 512;
static constexpr int G = 4;
static constexpr int D = 64;
static constexpr int THREADS = 256;
static constexpr int CHUNKS = D / 8;            // 8 threads per row
static constexpr int ROWS_PER_IT = THREADS / CHUNKS;  // 32 copy-rows per iteration

__device__ __forceinline__ void stg256(float* p, const float v[8])
{
    asm volatile(
        "st.global.v8.b32 [%0], {%1,%2,%3,%4,%5,%6,%7,%8};"
        :: "l"(p),
           "r"(__float_as_uint(v[0])), "r"(__float_as_uint(v[1])),
           "r"(__float_as_uint(v[2])), "r"(__float_as_uint(v[3])),
           "r"(__float_as_uint(v[4])), "r"(__float_as_uint(v[5])),
           "r"(__float_as_uint(v[6])), "r"(__float_as_uint(v[7]))
        : "memory");
}

__global__ void __launch_bounds__(THREADS, 8)
gembed_bcast_kernel(const int* __restrict__ GE,
                    const float* __restrict__ W,
                    const float* __restrict__ b,
                    float* __restrict__ out)
{
    const int pair  = blockIdx.x;          // v*G + g, 0..2047
    const int t     = threadIdx.x;         // 0..255
    const int chunk = t & (CHUNKS - 1);    // which 8-float chunk of the row
    const int r0    = t >> 3;              // starting copy row (0..31)

    const int idx = GE[pair] % 3;          // GE in [0,3)

    // This thread's 8 floats of the embedding row: W[idx, chunk*8 .. +8] + b[...]
    const float4 w0 = reinterpret_cast<const float4*>(W + idx * D)[chunk * 2 + 0];
    const float4 w1 = reinterpret_cast<const float4*>(W + idx * D)[chunk * 2 + 1];
    const float4 b0 = reinterpret_cast<const float4*>(b)[chunk * 2 + 0];
    const float4 b1 = reinterpret_cast<const float4*>(b)[chunk * 2 + 1];

    float val[8];
    val[0] = w0.x + b0.x;  val[1] = w0.y + b0.y;
    val[2] = w0.z + b0.z;  val[3] = w0.w + b0.w;
    val[4] = w1.x + b1.x;  val[5] = w1.y + b1.y;
    val[6] = w1.z + b1.z;  val[7] = w1.w + b1.w;

    // Stream 512 copies of the row. Warp writes 1 KB contiguous per
    // instruction; each thread issues 16 x STG.256.
    float* base = out + (size_t)pair * (size_t)(V * D) + (size_t)(chunk * 8);

    #pragma unroll
    for (int r = r0; r < V; r += ROWS_PER_IT) {
        stg256(base + r * D, val);
    }
}

extern "C" void kernel_launch(void* const* d_in, const int* in_sizes, int n_in,
                              void* d_out, int out_size)
{
    const int*   GE = (const int*)d_in[0];
    const float* W  = (const float*)d_in[1];
    const float* b  = (const float*)d_in[2];
    float* out = (float*)d_out;

    (void)in_sizes; (void)n_in; (void)out_size;

    gembed_bcast_kernel<<<V * G, THREADS>>>(GE, W, b, out);
}